// round 4
// baseline (speedup 1.0000x reference)
#include <cuda_runtime.h>

#define BATCH 16384
#define EMBED 300
#define NCTX  10
#define NNEG  20
#define NSC   (1 + NNEG)      // 21 scores
#define NF4   75              // 300 floats = 75 float4 per row
#define B_PER_BLOCK 4
#define WARPS_PER_BLOCK (B_PER_BLOCK * 2)   // 2 warps per batch element
#define BLOCK_THREADS   (WARPS_PER_BLOCK * 32)  // 256
#define GRID_BLOCKS     (BATCH / B_PER_BLOCK)    // 4096

// fused-reduction state (zero-init .bss; last block resets for graph replays)
__device__ float        g_sum;
__device__ unsigned int g_arrived;

__device__ __forceinline__ float log_sigmoid(float x) {
    return fminf(x, 0.0f) - log1pf(__expf(-fabsf(x)));
}

__device__ __forceinline__ float dot4(float4 a, float4 b) {
    return a.x * b.x + a.y * b.y + a.z * b.z + a.w * b.w;
}

__global__ __launch_bounds__(BLOCK_THREADS)
void cbow_fused_kernel(const int*   __restrict__ context,    // [B, NCTX]
                       const int*   __restrict__ center,     // [B]
                       const int*   __restrict__ negatives,  // [B, NNEG]
                       const float* __restrict__ ctx_w,      // [V, 300]
                       const float* __restrict__ cen_w,      // [V, 300]
                       float*       __restrict__ out)
{
    const int warp = threadIdx.x >> 5;
    const int lane = threadIdx.x & 31;
    const int half = warp & 1;                       // 0: slots [0..31]+[64..69], 1: [32..63]+[70..74]
    const int b    = blockIdx.x * B_PER_BLOCK + (warp >> 1);

    // per-warp float4 slot assignment (sector-disjoint between halves)
    const int  slot0   = half ? (32 + lane) : lane;
    const int  slotT   = half ? (70 + lane) : (64 + lane);
    const bool tail_ok = half ? (lane < 5) : (lane < 6);

    // ---- all 31 indices for this b, one per lane (both warps load a copy) ----
    int idx = 0;
    if (lane < NCTX)            idx = context[b * NCTX + lane];
    else if (lane == NCTX)      idx = center[b];
    else if (lane < NCTX + NSC) idx = negatives[b * NNEG + (lane - NCTX - 1)];

    // ---- context mean (this warp's half-row) ----
    float4 cm0 = make_float4(0.f, 0.f, 0.f, 0.f);
    float4 cmT = cm0;

    #pragma unroll
    for (int c = 0; c < NCTX; ++c) {
        int row = __shfl_sync(0xffffffffu, idx, c);
        const float4* r = reinterpret_cast<const float4*>(ctx_w + (size_t)row * EMBED);
        float4 a0 = __ldg(r + slot0);
        cm0.x += a0.x; cm0.y += a0.y; cm0.z += a0.z; cm0.w += a0.w;
        if (tail_ok) {
            float4 aT = __ldg(r + slotT);
            cmT.x += aT.x; cmT.y += aT.y; cmT.z += aT.z; cmT.w += aT.w;
        }
    }
    const float inv_c = 1.0f / (float)NCTX;
    cm0.x *= inv_c; cm0.y *= inv_c; cm0.z *= inv_c; cm0.w *= inv_c;
    cmT.x *= inv_c; cmT.y *= inv_c; cmT.z *= inv_c; cmT.w *= inv_c;

    // ---- 21 partial scores (this half-row), no per-t sync ----
    __shared__ float sh_s[WARPS_PER_BLOCK][NSC];

    #pragma unroll
    for (int t = 0; t < NSC; ++t) {
        int row = __shfl_sync(0xffffffffu, idx, NCTX + t);
        const float4* r = reinterpret_cast<const float4*>(cen_w + (size_t)row * EMBED);
        float4 a0 = __ldg(r + slot0);
        float s = dot4(a0, cm0);
        if (tail_ok) {
            float4 aT = __ldg(r + slotT);
            s += dot4(aT, cmT);
        }
        #pragma unroll
        for (int off = 16; off > 0; off >>= 1)
            s += __shfl_xor_sync(0xffffffffu, s, off);
        if (lane == 0) sh_s[warp][t] = s;
    }
    __syncthreads();

    // ---- even warps: combine halves, log-sigmoid one-per-lane, warp-reduce ----
    __shared__ float sdata[B_PER_BLOCK];
    if (half == 0) {
        float l = 0.0f;
        if (lane < NSC) {
            float s = sh_s[warp][lane] + sh_s[warp + 1][lane];
            l = log_sigmoid(lane == 0 ? s : -s);
        }
        #pragma unroll
        for (int off = 16; off > 0; off >>= 1)
            l += __shfl_xor_sync(0xffffffffu, l, off);
        if (lane == 0) sdata[warp >> 1] = -l;
    }
    __syncthreads();

    // ---- fused grid reduction: last block finalizes ----
    if (threadIdx.x == 0) {
        float tot = 0.f;
        #pragma unroll
        for (int i = 0; i < B_PER_BLOCK; ++i) tot += sdata[i];

        atomicAdd(&g_sum, tot);
        __threadfence();
        unsigned prev = atomicAdd(&g_arrived, 1u);
        if (prev == GRID_BLOCKS - 1) {
            float total = g_sum;
            out[0] = total / (float)BATCH;
            g_sum = 0.0f;
            __threadfence();
            g_arrived = 0u;
        }
    }
}

extern "C" void kernel_launch(void* const* d_in, const int* in_sizes, int n_in,
                              void* d_out, int out_size)
{
    const int*   context   = (const int*)  d_in[0];
    const int*   center    = (const int*)  d_in[1];
    const int*   negatives = (const int*)  d_in[2];
    const float* ctx_w     = (const float*)d_in[3];
    const float* cen_w     = (const float*)d_in[4];
    float*       out       = (float*)d_out;

    cbow_fused_kernel<<<GRID_BLOCKS, BLOCK_THREADS>>>(
        context, center, negatives, ctx_w, cen_w, out);
}

// round 5
// speedup vs baseline: 1.1025x; 1.1025x over previous
#include <cuda_runtime.h>
#include <cuda_bf16.h>

#define BATCH 16384
#define EMBED 300
#define NCTX  10
#define NNEG  20
#define NSC   (1 + NNEG)
#define NF4   75           // 300 floats = 75 float4 slots per row
#define WARPS_PER_BLOCK 8
#define BLOCK_THREADS   (WARPS_PER_BLOCK * 32)
#define GRID_BLOCKS     (BATCH / WARPS_PER_BLOCK)   // 2048

// context means stored as bf16: per slot 4 bf16 packed in uint2 (9.83 MB total)
__device__ uint2 g_cm[BATCH * NF4];

// fused-reduction state (zero-init .bss; last block resets for graph replays)
__device__ float        g_sum;
__device__ unsigned int g_arrived;

__device__ __forceinline__ float log_sigmoid(float x) {
    return fminf(x, 0.0f) - log1pf(__expf(-fabsf(x)));
}

__device__ __forceinline__ float dot4(float4 a, float4 b) {
    return a.x * b.x + a.y * b.y + a.z * b.z + a.w * b.w;
}

__device__ __forceinline__ uint2 pack_bf16x4(float4 v) {
    __nv_bfloat162 lo = __float22bfloat162_rn(make_float2(v.x, v.y));
    __nv_bfloat162 hi = __float22bfloat162_rn(make_float2(v.z, v.w));
    uint2 r;
    r.x = *reinterpret_cast<unsigned int*>(&lo);
    r.y = *reinterpret_cast<unsigned int*>(&hi);
    return r;
}

__device__ __forceinline__ float4 unpack_bf16x4(uint2 p) {
    __nv_bfloat162 lo = *reinterpret_cast<__nv_bfloat162*>(&p.x);
    __nv_bfloat162 hi = *reinterpret_cast<__nv_bfloat162*>(&p.y);
    float2 a = __bfloat1622float2(lo);
    float2 b = __bfloat1622float2(hi);
    return make_float4(a.x, a.y, b.x, b.y);
}

// ───────────── Phase A: ctx_w gathers only (working set ~97 MB < L2) ────────
__global__ __launch_bounds__(BLOCK_THREADS)
void cbow_ctx_mean_kernel(const int*   __restrict__ context,  // [B, NCTX]
                          const float* __restrict__ ctx_w)    // [V, 300]
{
    const int warp = threadIdx.x >> 5;
    const int lane = threadIdx.x & 31;
    const int b    = blockIdx.x * WARPS_PER_BLOCK + warp;

    int idx = 0;
    if (lane < NCTX) idx = context[b * NCTX + lane];

    float4 cm0 = make_float4(0.f, 0.f, 0.f, 0.f);
    float4 cm1 = cm0;
    float4 cm2 = cm0;
    const bool tail = (lane < NF4 - 64);   // lane < 11

    #pragma unroll
    for (int c = 0; c < NCTX; ++c) {
        int row = __shfl_sync(0xffffffffu, idx, c);
        const float4* r = reinterpret_cast<const float4*>(ctx_w + (size_t)row * EMBED);
        float4 a0 = __ldg(r + lane);
        float4 a1 = __ldg(r + lane + 32);
        cm0.x += a0.x; cm0.y += a0.y; cm0.z += a0.z; cm0.w += a0.w;
        cm1.x += a1.x; cm1.y += a1.y; cm1.z += a1.z; cm1.w += a1.w;
        if (tail) {
            float4 a2 = __ldg(r + lane + 64);
            cm2.x += a2.x; cm2.y += a2.y; cm2.z += a2.z; cm2.w += a2.w;
        }
    }
    const float inv_c = 1.0f / (float)NCTX;
    cm0.x *= inv_c; cm0.y *= inv_c; cm0.z *= inv_c; cm0.w *= inv_c;
    cm1.x *= inv_c; cm1.y *= inv_c; cm1.z *= inv_c; cm1.w *= inv_c;
    cm2.x *= inv_c; cm2.y *= inv_c; cm2.z *= inv_c; cm2.w *= inv_c;

    uint2* dst = g_cm + (size_t)b * NF4;
    dst[lane]      = pack_bf16x4(cm0);
    dst[lane + 32] = pack_bf16x4(cm1);
    if (tail) dst[lane + 64] = pack_bf16x4(cm2);
}

// ───────────── Phase B: cen_w gathers (working set ~116+10 MB ≈ L2) ─────────
__global__ __launch_bounds__(BLOCK_THREADS)
void cbow_score_kernel(const int*   __restrict__ center,     // [B]
                       const int*   __restrict__ negatives,  // [B, NNEG]
                       const float* __restrict__ cen_w,      // [V, 300]
                       float*       __restrict__ out)
{
    const int warp = threadIdx.x >> 5;
    const int lane = threadIdx.x & 31;
    const int b    = blockIdx.x * WARPS_PER_BLOCK + warp;

    // 21 indices: lane 0 = center, lanes 1..20 = negatives
    int idx = 0;
    if (lane == 0)         idx = center[b];
    else if (lane <= NNEG) idx = negatives[b * NNEG + (lane - 1)];

    // load context mean (bf16 -> f32)
    const uint2* src = g_cm + (size_t)b * NF4;
    const bool tail = (lane < NF4 - 64);
    float4 cm0 = unpack_bf16x4(src[lane]);
    float4 cm1 = unpack_bf16x4(src[lane + 32]);
    float4 cm2 = tail ? unpack_bf16x4(src[lane + 64])
                      : make_float4(0.f, 0.f, 0.f, 0.f);

    float loss = 0.0f;
    #pragma unroll
    for (int t = 0; t < NSC; ++t) {
        int row = __shfl_sync(0xffffffffu, idx, t);
        const float4* r = reinterpret_cast<const float4*>(cen_w + (size_t)row * EMBED);
        float4 a0 = __ldg(r + lane);
        float4 a1 = __ldg(r + lane + 32);
        float s = dot4(a0, cm0) + dot4(a1, cm1);
        if (tail) {
            float4 a2 = __ldg(r + lane + 64);
            s += dot4(a2, cm2);
        }
        #pragma unroll
        for (int off = 16; off > 0; off >>= 1)
            s += __shfl_xor_sync(0xffffffffu, s, off);
        loss += log_sigmoid(t == 0 ? s : -s);
    }

    __shared__ float sdata[WARPS_PER_BLOCK];
    if (lane == 0) sdata[warp] = -loss;
    __syncthreads();

    if (threadIdx.x == 0) {
        float tot = 0.f;
        #pragma unroll
        for (int i = 0; i < WARPS_PER_BLOCK; ++i) tot += sdata[i];

        atomicAdd(&g_sum, tot);
        __threadfence();
        unsigned prev = atomicAdd(&g_arrived, 1u);
        if (prev == GRID_BLOCKS - 1) {
            float total = g_sum;
            out[0] = total / (float)BATCH;
            g_sum = 0.0f;
            __threadfence();
            g_arrived = 0u;
        }
    }
}

extern "C" void kernel_launch(void* const* d_in, const int* in_sizes, int n_in,
                              void* d_out, int out_size)
{
    const int*   context   = (const int*)  d_in[0];
    const int*   center    = (const int*)  d_in[1];
    const int*   negatives = (const int*)  d_in[2];
    const float* ctx_w     = (const float*)d_in[3];
    const float* cen_w     = (const float*)d_in[4];
    float*       out       = (float*)d_out;

    cbow_ctx_mean_kernel<<<GRID_BLOCKS, BLOCK_THREADS>>>(context, ctx_w);
    cbow_score_kernel<<<GRID_BLOCKS, BLOCK_THREADS>>>(center, negatives, cen_w, out);
}

// round 6
// speedup vs baseline: 1.1044x; 1.0017x over previous
#include <cuda_runtime.h>
#include <cuda_bf16.h>

#define BATCH 16384
#define EMBED 300
#define NCTX  10
#define NNEG  20
#define NSC   (1 + NNEG)   // 21 scores
#define NCHUNK 3
#define CHW    7           // 3 * 7 = 21
#define NF4   75           // 300 floats = 75 float4 slots per row
#define WARPS_PER_BLOCK 8
#define BLOCK_THREADS   (WARPS_PER_BLOCK * 32)
#define GRID_BLOCKS     (BATCH / WARPS_PER_BLOCK)   // 2048

// context means stored as bf16: per slot 4 bf16 packed in uint2 (9.83 MB total)
__device__ uint2 g_cm[BATCH * NF4];

// fused-reduction state (zero-init .bss; last block resets for graph replays)
__device__ float        g_sum;
__device__ unsigned int g_arrived;

__device__ __forceinline__ float log_sigmoid(float x) {
    return fminf(x, 0.0f) - log1pf(__expf(-fabsf(x)));
}

__device__ __forceinline__ float dot4(float4 a, float4 b) {
    return a.x * b.x + a.y * b.y + a.z * b.z + a.w * b.w;
}

__device__ __forceinline__ uint2 pack_bf16x4(float4 v) {
    __nv_bfloat162 lo = __float22bfloat162_rn(make_float2(v.x, v.y));
    __nv_bfloat162 hi = __float22bfloat162_rn(make_float2(v.z, v.w));
    uint2 r;
    r.x = *reinterpret_cast<unsigned int*>(&lo);
    r.y = *reinterpret_cast<unsigned int*>(&hi);
    return r;
}

__device__ __forceinline__ float4 unpack_bf16x4(uint2 p) {
    __nv_bfloat162 lo = *reinterpret_cast<__nv_bfloat162*>(&p.x);
    __nv_bfloat162 hi = *reinterpret_cast<__nv_bfloat162*>(&p.y);
    float2 a = __bfloat1622float2(lo);
    float2 b = __bfloat1622float2(hi);
    return make_float4(a.x, a.y, b.x, b.y);
}

// ───────────── Phase A: ctx_w gathers only (working set ~97 MB < L2) ────────
__global__ __launch_bounds__(BLOCK_THREADS)
void cbow_ctx_mean_kernel(const int*   __restrict__ context,  // [B, NCTX]
                          const float* __restrict__ ctx_w)    // [V, 300]
{
    const int warp = threadIdx.x >> 5;
    const int lane = threadIdx.x & 31;
    const int b    = blockIdx.x * WARPS_PER_BLOCK + warp;

    int idx = 0;
    if (lane < NCTX) idx = context[b * NCTX + lane];

    float4 cm0 = make_float4(0.f, 0.f, 0.f, 0.f);
    float4 cm1 = cm0;
    float4 cm2 = cm0;
    const bool tail = (lane < NF4 - 64);   // lane < 11

    #pragma unroll
    for (int c = 0; c < NCTX; ++c) {
        int row = __shfl_sync(0xffffffffu, idx, c);
        const float4* r = reinterpret_cast<const float4*>(ctx_w + (size_t)row * EMBED);
        float4 a0 = __ldg(r + lane);
        float4 a1 = __ldg(r + lane + 32);
        cm0.x += a0.x; cm0.y += a0.y; cm0.z += a0.z; cm0.w += a0.w;
        cm1.x += a1.x; cm1.y += a1.y; cm1.z += a1.z; cm1.w += a1.w;
        if (tail) {
            float4 a2 = __ldg(r + lane + 64);
            cm2.x += a2.x; cm2.y += a2.y; cm2.z += a2.z; cm2.w += a2.w;
        }
    }
    const float inv_c = 1.0f / (float)NCTX;
    cm0.x *= inv_c; cm0.y *= inv_c; cm0.z *= inv_c; cm0.w *= inv_c;
    cm1.x *= inv_c; cm1.y *= inv_c; cm1.z *= inv_c; cm1.w *= inv_c;
    cm2.x *= inv_c; cm2.y *= inv_c; cm2.z *= inv_c; cm2.w *= inv_c;

    uint2* dst = g_cm + (size_t)b * NF4;
    dst[lane]      = pack_bf16x4(cm0);
    dst[lane + 32] = pack_bf16x4(cm1);
    if (tail) dst[lane + 64] = pack_bf16x4(cm2);
}

// ───────────── Phase B: cen_w gathers, chunked parallel reduction ───────────
__global__ __launch_bounds__(BLOCK_THREADS)
void cbow_score_kernel(const int*   __restrict__ center,     // [B]
                       const int*   __restrict__ negatives,  // [B, NNEG]
                       const float* __restrict__ cen_w,      // [V, 300]
                       float*       __restrict__ out)
{
    const int warp = threadIdx.x >> 5;
    const int lane = threadIdx.x & 31;
    const int b    = blockIdx.x * WARPS_PER_BLOCK + warp;

    // 21 indices: lane 0 = center (t=0), lanes 1..20 = negatives
    int idx = 0;
    if (lane == 0)         idx = center[b];
    else if (lane <= NNEG) idx = negatives[b * NNEG + (lane - 1)];

    // load context mean (bf16 -> f32)
    const uint2* src = g_cm + (size_t)b * NF4;
    const bool tail = (lane < NF4 - 64);
    float4 cm0 = unpack_bf16x4(src[lane]);
    float4 cm1 = unpack_bf16x4(src[lane + 32]);
    float4 cm2 = tail ? unpack_bf16x4(src[lane + 64])
                      : make_float4(0.f, 0.f, 0.f, 0.f);

    float loss = 0.0f;

    #pragma unroll
    for (int ch = 0; ch < NCHUNK; ++ch) {
        // 1) 7 per-lane partial scores — all 21 loads independent (max MLP)
        float s[CHW];
        #pragma unroll
        for (int j = 0; j < CHW; ++j) {
            int t   = ch * CHW + j;
            int row = __shfl_sync(0xffffffffu, idx, t);
            const float4* r = reinterpret_cast<const float4*>(cen_w + (size_t)row * EMBED);
            float4 a0 = __ldg(r + lane);
            float4 a1 = __ldg(r + lane + 32);
            s[j] = dot4(a0, cm0) + dot4(a1, cm1);
            if (tail) {
                float4 a2 = __ldg(r + lane + 64);
                s[j] += dot4(a2, cm2);
            }
        }
        // 2) one 5-level butterfly reduces all 7 simultaneously (7-way ILP)
        #pragma unroll
        for (int off = 16; off > 0; off >>= 1) {
            #pragma unroll
            for (int j = 0; j < CHW; ++j)
                s[j] += __shfl_xor_sync(0xffffffffu, s[j], off);
        }
        // 3) lanes 0..6 each take one score; log-sigmoids run in parallel
        if (lane < CHW) {
            float v = s[0];
            #pragma unroll
            for (int j = 1; j < CHW; ++j)
                if (lane == j) v = s[j];
            int t = ch * CHW + lane;
            loss += log_sigmoid(t == 0 ? v : -v);
        }
    }

    // final warp reduction of loss (lanes >= 7 hold 0)
    #pragma unroll
    for (int off = 16; off > 0; off >>= 1)
        loss += __shfl_xor_sync(0xffffffffu, loss, off);

    __shared__ float sdata[WARPS_PER_BLOCK];
    if (lane == 0) sdata[warp] = -loss;
    __syncthreads();

    if (threadIdx.x == 0) {
        float tot = 0.f;
        #pragma unroll
        for (int i = 0; i < WARPS_PER_BLOCK; ++i) tot += sdata[i];

        atomicAdd(&g_sum, tot);
        __threadfence();
        unsigned prev = atomicAdd(&g_arrived, 1u);
        if (prev == GRID_BLOCKS - 1) {
            float total = g_sum;
            out[0] = total / (float)BATCH;
            g_sum = 0.0f;
            __threadfence();
            g_arrived = 0u;
        }
    }
}

extern "C" void kernel_launch(void* const* d_in, const int* in_sizes, int n_in,
                              void* d_out, int out_size)
{
    const int*   context   = (const int*)  d_in[0];
    const int*   center    = (const int*)  d_in[1];
    const int*   negatives = (const int*)  d_in[2];
    const float* ctx_w     = (const float*)d_in[3];
    const float* cen_w     = (const float*)d_in[4];
    float*       out       = (float*)d_out;

    cbow_ctx_mean_kernel<<<GRID_BLOCKS, BLOCK_THREADS>>>(context, ctx_w);
    cbow_score_kernel<<<GRID_BLOCKS, BLOCK_THREADS>>>(center, negatives, cen_w, out);
}

// round 7
// speedup vs baseline: 1.1312x; 1.0243x over previous
#include <cuda_runtime.h>

#define BATCH 16384
#define EMBED 300
#define NCTX  10
#define NNEG  20
#define NSC   (1 + NNEG)   // 21 scores
#define NF4   75           // 300 floats = 75 float4 slots per row
#define WARPS_PER_BLOCK 8
#define BLOCK_THREADS   (WARPS_PER_BLOCK * 32)
#define GRID_BLOCKS     (BATCH / WARPS_PER_BLOCK)   // 2048
#define MIN_BLOCKS_SM   6                            // force regs <= 42

// fused-reduction state (zero-init .bss; last block resets for graph replays)
__device__ float        g_sum;
__device__ unsigned int g_arrived;

__device__ __forceinline__ float log_sigmoid(float x) {
    return fminf(x, 0.0f) - log1pf(__expf(-fabsf(x)));
}

__device__ __forceinline__ float dot4(float4 a, float4 b) {
    return a.x * b.x + a.y * b.y + a.z * b.z + a.w * b.w;
}

__global__ __launch_bounds__(BLOCK_THREADS, MIN_BLOCKS_SM)
void cbow_fused_kernel(const int*   __restrict__ context,    // [B, NCTX]
                       const int*   __restrict__ center,     // [B]
                       const int*   __restrict__ negatives,  // [B, NNEG]
                       const float* __restrict__ ctx_w,      // [V, 300]
                       const float* __restrict__ cen_w,      // [V, 300]
                       float*       __restrict__ out)
{
    const int warp = threadIdx.x >> 5;
    const int lane = threadIdx.x & 31;
    const int b    = blockIdx.x * WARPS_PER_BLOCK + warp;

    // ---- all 31 indices for this b, one per lane ----
    int idx = 0;
    if (lane < NCTX)            idx = context[b * NCTX + lane];
    else if (lane == NCTX)      idx = center[b];
    else if (lane < NCTX + NSC) idx = negatives[b * NNEG + (lane - NCTX - 1)];

    // ---- context mean: lane covers float4 slots {lane, lane+32, lane+64} ----
    float4 cm0 = make_float4(0.f, 0.f, 0.f, 0.f);
    float4 cm1 = cm0;
    float4 cm2 = cm0;
    const bool tail = (lane < NF4 - 64);   // lane < 11

    #pragma unroll
    for (int c = 0; c < NCTX; ++c) {
        int row = __shfl_sync(0xffffffffu, idx, c);
        const float4* r = reinterpret_cast<const float4*>(ctx_w + (size_t)row * EMBED);
        float4 a0 = __ldg(r + lane);
        float4 a1 = __ldg(r + lane + 32);
        cm0.x += a0.x; cm0.y += a0.y; cm0.z += a0.z; cm0.w += a0.w;
        cm1.x += a1.x; cm1.y += a1.y; cm1.z += a1.z; cm1.w += a1.w;
        if (tail) {
            float4 a2 = __ldg(r + lane + 64);
            cm2.x += a2.x; cm2.y += a2.y; cm2.z += a2.z; cm2.w += a2.w;
        }
    }
    const float inv_c = 1.0f / (float)NCTX;
    cm0.x *= inv_c; cm0.y *= inv_c; cm0.z *= inv_c; cm0.w *= inv_c;
    cm1.x *= inv_c; cm1.y *= inv_c; cm1.z *= inv_c; cm1.w *= inv_c;
    cm2.x *= inv_c; cm2.y *= inv_c; cm2.z *= inv_c; cm2.w *= inv_c;

    // ---- 21 scores; each t terminates in smem (no cross-t register dep) ----
    __shared__ float sh_s[WARPS_PER_BLOCK][NSC];

    #pragma unroll
    for (int t = 0; t < NSC; ++t) {
        int row = __shfl_sync(0xffffffffu, idx, NCTX + t);
        const float4* r = reinterpret_cast<const float4*>(cen_w + (size_t)row * EMBED);
        float4 a0 = __ldg(r + lane);
        float4 a1 = __ldg(r + lane + 32);
        float s = dot4(a0, cm0) + dot4(a1, cm1);
        if (tail) {
            float4 a2 = __ldg(r + lane + 64);
            s += dot4(a2, cm2);
        }
        #pragma unroll
        for (int off = 16; off > 0; off >>= 1)
            s += __shfl_xor_sync(0xffffffffu, s, off);
        if (lane == 0) sh_s[warp][t] = s;
    }
    __syncwarp();

    // ---- parallel log-sigmoids: one per lane ----
    float l = 0.0f;
    if (lane < NSC) {
        float s = sh_s[warp][lane];
        l = log_sigmoid(lane == 0 ? s : -s);
    }
    #pragma unroll
    for (int off = 16; off > 0; off >>= 1)
        l += __shfl_xor_sync(0xffffffffu, l, off);

    __shared__ float sdata[WARPS_PER_BLOCK];
    if (lane == 0) sdata[warp] = -l;
    __syncthreads();

    // ---- fused grid reduction: last block finalizes ----
    if (threadIdx.x == 0) {
        float tot = 0.f;
        #pragma unroll
        for (int i = 0; i < WARPS_PER_BLOCK; ++i) tot += sdata[i];

        atomicAdd(&g_sum, tot);
        __threadfence();
        unsigned prev = atomicAdd(&g_arrived, 1u);
        if (prev == GRID_BLOCKS - 1) {
            float total = g_sum;
            out[0] = total / (float)BATCH;
            g_sum = 0.0f;
            __threadfence();
            g_arrived = 0u;
        }
    }
}

extern "C" void kernel_launch(void* const* d_in, const int* in_sizes, int n_in,
                              void* d_out, int out_size)
{
    const int*   context   = (const int*)  d_in[0];
    const int*   center    = (const int*)  d_in[1];
    const int*   negatives = (const int*)  d_in[2];
    const float* ctx_w     = (const float*)d_in[3];
    const float* cen_w     = (const float*)d_in[4];
    float*       out       = (float*)d_out;

    cbow_fused_kernel<<<GRID_BLOCKS, BLOCK_THREADS>>>(
        context, center, negatives, ctx_w, cen_w, out);
}

// round 10
// speedup vs baseline: 1.1683x; 1.0328x over previous
#include <cuda_runtime.h>

#define BATCH 16384
#define EMBED 300
#define NCTX  10
#define NNEG  20
#define NSC   (1 + NNEG)   // 21 scores
#define NF4   75           // 300 floats = 75 float4 slots per row
#define WARPS_PER_BLOCK 8
#define BLOCK_THREADS   (WARPS_PER_BLOCK * 32)
#define GRID_BLOCKS     (BATCH / WARPS_PER_BLOCK)   // 2048
#define MIN_BLOCKS_SM   6

// fused-reduction state (zero-init .bss; last block resets for graph replays)
__device__ float        g_sum;
__device__ unsigned int g_arrived;

__device__ __forceinline__ float log_sigmoid(float x) {
    return fminf(x, 0.0f) - log1pf(__expf(-fabsf(x)));
}

__device__ __forceinline__ float dot4(float4 a, float4 b) {
    return a.x * b.x + a.y * b.y + a.z * b.z + a.w * b.w;
}

// cache-policy descriptors (createpolicy works with any load width via cache_hint)
__device__ __forceinline__ unsigned long long policy_evict_first() {
    unsigned long long p;
    asm("createpolicy.fractional.L2::evict_first.b64 %0, 1.0;" : "=l"(p));
    return p;
}
__device__ __forceinline__ unsigned long long policy_evict_last() {
    unsigned long long p;
    asm("createpolicy.fractional.L2::evict_last.b64 %0, 1.0;" : "=l"(p));
    return p;
}

__device__ __forceinline__ float4 ldg_hint(const float4* p, unsigned long long pol) {
    float4 v;
    asm("ld.global.nc.L2::cache_hint.v4.f32 {%0,%1,%2,%3}, [%4], %5;"
        : "=f"(v.x), "=f"(v.y), "=f"(v.z), "=f"(v.w)
        : "l"(p), "l"(pol));
    return v;
}

__global__ __launch_bounds__(BLOCK_THREADS, MIN_BLOCKS_SM)
void cbow_fused_kernel(const int*   __restrict__ context,    // [B, NCTX]
                       const int*   __restrict__ center,     // [B]
                       const int*   __restrict__ negatives,  // [B, NNEG]
                       const float* __restrict__ ctx_w,      // [V, 300]
                       const float* __restrict__ cen_w,      // [V, 300]
                       float*       __restrict__ out)
{
    const int warp = threadIdx.x >> 5;
    const int lane = threadIdx.x & 31;
    const int b    = blockIdx.x * WARPS_PER_BLOCK + warp;

    const unsigned long long pol_stream   = policy_evict_first();
    const unsigned long long pol_resident = policy_evict_last();

    // ---- all 31 indices for this b, one per lane ----
    int idx = 0;
    if (lane < NCTX)            idx = context[b * NCTX + lane];
    else if (lane == NCTX)      idx = center[b];
    else if (lane < NCTX + NSC) idx = negatives[b * NNEG + (lane - NCTX - 1)];

    // ---- context mean: lane covers float4 slots {lane, lane+32, lane+64} ----
    float4 cm0 = make_float4(0.f, 0.f, 0.f, 0.f);
    float4 cm1 = cm0;
    float4 cm2 = cm0;
    const bool tail = (lane < NF4 - 64);   // lane < 11

    #pragma unroll
    for (int c = 0; c < NCTX; ++c) {
        int row = __shfl_sync(0xffffffffu, idx, c);
        const float4* r = reinterpret_cast<const float4*>(ctx_w + (size_t)row * EMBED);
        float4 a0 = ldg_hint(r + lane,      pol_stream);
        float4 a1 = ldg_hint(r + lane + 32, pol_stream);
        cm0.x += a0.x; cm0.y += a0.y; cm0.z += a0.z; cm0.w += a0.w;
        cm1.x += a1.x; cm1.y += a1.y; cm1.z += a1.z; cm1.w += a1.w;
        if (tail) {
            float4 a2 = ldg_hint(r + lane + 64, pol_stream);
            cm2.x += a2.x; cm2.y += a2.y; cm2.z += a2.z; cm2.w += a2.w;
        }
    }
    const float inv_c = 1.0f / (float)NCTX;
    cm0.x *= inv_c; cm0.y *= inv_c; cm0.z *= inv_c; cm0.w *= inv_c;
    cm1.x *= inv_c; cm1.y *= inv_c; cm1.z *= inv_c; cm1.w *= inv_c;
    cm2.x *= inv_c; cm2.y *= inv_c; cm2.z *= inv_c; cm2.w *= inv_c;

    // ---- 21 scores; each t terminates in smem (no cross-t register dep) ----
    __shared__ float sh_s[WARPS_PER_BLOCK][NSC];

    #pragma unroll
    for (int t = 0; t < NSC; ++t) {
        int row = __shfl_sync(0xffffffffu, idx, NCTX + t);
        const float4* r = reinterpret_cast<const float4*>(cen_w + (size_t)row * EMBED);
        float4 a0 = ldg_hint(r + lane,      pol_resident);
        float4 a1 = ldg_hint(r + lane + 32, pol_resident);
        float s = dot4(a0, cm0) + dot4(a1, cm1);
        if (tail) {
            float4 a2 = ldg_hint(r + lane + 64, pol_resident);
            s += dot4(a2, cm2);
        }
        #pragma unroll
        for (int off = 16; off > 0; off >>= 1)
            s += __shfl_xor_sync(0xffffffffu, s, off);
        if (lane == 0) sh_s[warp][t] = s;
    }
    __syncwarp();

    // ---- parallel log-sigmoids: one per lane ----
    float l = 0.0f;
    if (lane < NSC) {
        float s = sh_s[warp][lane];
        l = log_sigmoid(lane == 0 ? s : -s);
    }
    #pragma unroll
    for (int off = 16; off > 0; off >>= 1)
        l += __shfl_xor_sync(0xffffffffu, l, off);

    __shared__ float sdata[WARPS_PER_BLOCK];
    if (lane == 0) sdata[warp] = -l;
    __syncthreads();

    // ---- fused grid reduction: last block finalizes ----
    if (threadIdx.x == 0) {
        float tot = 0.f;
        #pragma unroll
        for (int i = 0; i < WARPS_PER_BLOCK; ++i) tot += sdata[i];

        atomicAdd(&g_sum, tot);
        __threadfence();
        unsigned prev = atomicAdd(&g_arrived, 1u);
        if (prev == GRID_BLOCKS - 1) {
            float total = g_sum;
            out[0] = total / (float)BATCH;
            g_sum = 0.0f;
            __threadfence();
            g_arrived = 0u;
        }
    }
}

extern "C" void kernel_launch(void* const* d_in, const int* in_sizes, int n_in,
                              void* d_out, int out_size)
{
    const int*   context   = (const int*)  d_in[0];
    const int*   center    = (const int*)  d_in[1];
    const int*   negatives = (const int*)  d_in[2];
    const float* ctx_w     = (const float*)d_in[3];
    const float* cen_w     = (const float*)d_in[4];
    float*       out       = (float*)d_out;

    cbow_fused_kernel<<<GRID_BLOCKS, BLOCK_THREADS>>>(
        context, center, negatives, ctx_w, cen_w, out);
}